// round 6
// baseline (speedup 1.0000x reference)
#include <cuda_runtime.h>
#include <cuda_bf16.h>
#include <cstdint>

// FlaxHouseholderRoPE: B=2, S=4096, H=32, D=128, R=2, fp32. SINGLE launch.
// Blocks 0..511 build g_tab (2MB cos/sin), blocks 512..519 build g_u
// (normalized reflectors); all 32768 blocks then run the streaming
// Householder+RoPE after a flag spin (acquire/release, counter reset by the
// last block so every graph replay does identical work).

#define SS 4096
#define HH 32
#define NVEC (2 * SS * HH)        // 262144 vectors per tensor
#define GRID (NVEC / 8)           // 32768 blocks
#define TAB_BLOCKS 512
#define NBUILD (TAB_BLOCKS + 8)   // 520

__device__ float4 g_tab[SS * 32];      // (cos,sin,cos,sin) per (s,lane)
__device__ float4 g_u[HH * 2 * 32];    // v * sqrt(2/(|v|^2+eps))
__device__ int    g_ready;             // zero-initialized
__device__ int    g_done;

__device__ __forceinline__ float dot4(float4 a, float4 b) {
    return a.x * b.x + a.y * b.y + a.z * b.z + a.w * b.w;
}

__global__ __launch_bounds__(256)
void hh_rope_kernel(const float* __restrict__ q,
                    const float* __restrict__ k,
                    const float* __restrict__ pos,
                    const float* __restrict__ refl,
                    float* __restrict__ out) {
    const int tid  = threadIdx.x;
    const int warp = tid >> 5;
    const int lane = tid & 31;
    const int idx  = blockIdx.x * 8 + warp;          // (b*S+s)*H + h
    const int h    = idx & (HH - 1);
    const int s    = (idx >> 5) & (SS - 1);

    // ================= builder phase (blocks 0..519) =================
    if (blockIdx.x < TAB_BLOCKS) {
        // one table entry per thread: 2 sincosf + 2 exp2f
        const int j  = blockIdx.x * 256 + tid;       // 0..131071
        const int ss = j >> 5;
        const int t  = j & 31;
        const float p = pos[ss];
        const float LOG2_BASE = 13.287712379549449f; // log2(10000)
        const float f0 = exp2f(-(float)(4 * t)     * (1.0f / 128.0f) * LOG2_BASE);
        const float f1 = exp2f(-(float)(4 * t + 2) * (1.0f / 128.0f) * LOG2_BASE);
        float s0, c0, s1, c1;
        sincosf(p * f0, &s0, &c0);
        sincosf(p * f1, &s1, &c1);
        g_tab[j] = make_float4(c0, s0, c1, s1);
        __threadfence();
        __syncthreads();
        if (tid == 0) { __threadfence(); atomicAdd(&g_ready, 1); }
    } else if (blockIdx.x < NBUILD) {
        // normalized reflectors: one row (h,r) per warp, 64 rows over 8 blocks
        const int row = (blockIdx.x - TAB_BLOCKS) * 8 + warp;   // 0..63
        const float4 v = reinterpret_cast<const float4*>(refl)[row * 32 + lane];
        float sq = dot4(v, v);
        #pragma unroll
        for (int o = 16; o; o >>= 1) sq += __shfl_xor_sync(0xffffffffu, sq, o);
        const float sc = sqrtf(2.0f / (sq + 1e-6f));
        g_u[row * 32 + lane] = make_float4(v.x * sc, v.y * sc, v.z * sc, v.w * sc);
        __threadfence();
        __syncthreads();
        if (tid == 0) { __threadfence(); atomicAdd(&g_ready, 1); }
    }

    // ========== streamed loads first (independent of builders) ==========
    const size_t off = (size_t)idx * 32 + lane;
    float4 xq = __ldcs(reinterpret_cast<const float4*>(q) + off);
    float4 xk = __ldcs(reinterpret_cast<const float4*>(k) + off);

    // ================= wait for builders =================
    if (tid == 0) {
        int r;
        while (true) {
            asm volatile("ld.acquire.gpu.b32 %0, [%1];"
                         : "=r"(r) : "l"(&g_ready) : "memory");
            if (r >= NBUILD) break;
            __nanosleep(64);
        }
    }
    __syncthreads();

    // ===== two normalized-Householder reflections on q and k =====
    #pragma unroll
    for (int r = 0; r < 2; ++r) {
        const float4 u = __ldcg(&g_u[(h * 2 + r) * 32 + lane]);
        float dq = dot4(xq, u);
        float dk = dot4(xk, u);
        #pragma unroll
        for (int o = 16; o; o >>= 1) {
            dq += __shfl_xor_sync(0xffffffffu, dq, o);
            dk += __shfl_xor_sync(0xffffffffu, dk, o);
        }
        xq.x -= dq * u.x;  xq.y -= dq * u.y;  xq.z -= dq * u.z;  xq.w -= dq * u.w;
        xk.x -= dk * u.x;  xk.y -= dk * u.y;  xk.z -= dk * u.z;  xk.w -= dk * u.w;
    }

    // ================= RoPE via table =================
    const float4 cs = __ldcg(&g_tab[s * 32 + lane]);   // (c0,s0,c1,s1)

    float4 oq, ok;
    oq.x = xq.x * cs.x - xq.y * cs.y;
    oq.y = xq.x * cs.y + xq.y * cs.x;
    oq.z = xq.z * cs.z - xq.w * cs.w;
    oq.w = xq.z * cs.w + xq.w * cs.z;
    ok.x = xk.x * cs.x - xk.y * cs.y;
    ok.y = xk.x * cs.y + xk.y * cs.x;
    ok.z = xk.z * cs.z - xk.w * cs.w;
    ok.w = xk.z * cs.w + xk.w * cs.z;

    float4* out4 = reinterpret_cast<float4*>(out);
    __stcs(out4 + off, oq);                              // q half
    __stcs(out4 + (size_t)NVEC * 32 + off, ok);          // k half

    // ===== reset counters for the next graph replay (last block) =====
    if (tid == 0) {
        const int d = atomicAdd(&g_done, 1);
        if (d == GRID - 1) {
            g_done  = 0;
            g_ready = 0;
            __threadfence();
        }
    }
}

extern "C" void kernel_launch(void* const* d_in, const int* in_sizes, int n_in,
                              void* d_out, int out_size) {
    const float* q    = (const float*)d_in[0];
    const float* k    = (const float*)d_in[1];
    const float* pos  = (const float*)d_in[2];
    const float* refl = (const float*)d_in[3];
    float* out = (float*)d_out;

    hh_rope_kernel<<<GRID, 256>>>(q, k, pos, refl, out);
}

// round 7
// speedup vs baseline: 1.0906x; 1.0906x over previous
#include <cuda_runtime.h>
#include <cuda_bf16.h>
#include <cstdint>

// FlaxHouseholderRoPE: B=2, S=4096, H=32, D=128, R=2, fp32. SINGLE kernel.
// Inputs: q (B,S,H,D), k (B,S,H,D), pos (S), reflectors (H,R,D)  [f32]
// Output: concat(q_out, k_out).
//
// One warp per (b,s,h), processing q AND k. All 8 warps of a block share the
// same (b,s): threads 0..63 build the 64 (cos,sin) pairs for this s in SMEM
// using Cody-Waite range reduction + MUFU sin/cos (~12 instrs, err ~1e-6,
// vs libdevice sincosf's Payne-Hanek slow path that sank round 5).
// Streamed loads are issued BEFORE the table build/barrier so they are in
// flight while the block synchronizes.
// Householder: fused 3-value butterfly (dot_q, dot_k, |v|^2) per reflection —
// bit-for-bit the reference recurrence: coef = 2*dot/(|v|^2+eps).

#define SS 4096
#define HH 32
#define NVEC (2 * SS * HH)        // 262144 vectors per tensor

__device__ __forceinline__ float dot4(float4 a, float4 b) {
    return a.x * b.x + a.y * b.y + a.z * b.z + a.w * b.w;
}

__global__ __launch_bounds__(256)
void hh_rope_kernel(const float* __restrict__ q,
                    const float* __restrict__ k,
                    const float* __restrict__ pos,
                    const float* __restrict__ refl,
                    float* __restrict__ out) {
    __shared__ float2 s_cs[64];   // (cos, sin) for pair j of this block's s

    const int tid  = threadIdx.x;
    const int warp = tid >> 5;
    const int lane = tid & 31;
    const int idx  = blockIdx.x * 8 + warp;          // (b*S+s)*H + h
    const int h    = idx & (HH - 1);
    const int s    = (idx >> 5) & (SS - 1);          // same for all 8 warps

    // ---- streamed loads FIRST (coalesced LDG.128, in flight across barrier) ----
    const size_t off = (size_t)idx * 32 + lane;
    float4 xq = __ldcs(reinterpret_cast<const float4*>(q) + off);
    float4 xk = __ldcs(reinterpret_cast<const float4*>(k) + off);

    // ---- per-block RoPE table: 64 pairs, cheap accurate sincos ----
    if (tid < 64) {
        const float LOG2_BASE = 13.287712379549449f;   // log2(10000)
        const float p  = pos[s];
        const float f  = exp2f(-(float)(2 * tid) * (1.0f / 128.0f) * LOG2_BASE);
        const float hi = p * f;                        // == reference's fp32 angle
        // Cody-Waite: hi <= 4096 -> n <= 652, n*C1 exact (10+5 mantissa bits)
        const float n  = rintf(hi * 0.15915494309189535f);   // hi / (2*pi)
        float r = fmaf(-n, 6.28125f, hi);              // exact (FMA, small result)
        r = fmaf(-n, 1.9353071795864769e-3f, r);       // |err| ~ 1e-7 rad
        s_cs[tid] = make_float2(__cosf(r), __sinf(r)); // MUFU on reduced range
    }
    __syncthreads();

    // ---- two sequential Householder reflections, fused 3-value butterfly ----
    #pragma unroll
    for (int r = 0; r < 2; ++r) {
        const float4 v = __ldg(reinterpret_cast<const float4*>(refl)
                               + (h * 2 + r) * 32 + lane);   // L1 hit after wave 1
        float dq = dot4(xq, v);
        float dk = dot4(xk, v);
        float sq = dot4(v, v);
        #pragma unroll
        for (int o = 16; o; o >>= 1) {
            dq += __shfl_xor_sync(0xffffffffu, dq, o);
            dk += __shfl_xor_sync(0xffffffffu, dk, o);
            sq += __shfl_xor_sync(0xffffffffu, sq, o);
        }
        const float inv = __frcp_rn(sq + 1e-6f);
        const float cq = 2.0f * dq * inv;
        const float ck = 2.0f * dk * inv;
        xq.x -= cq * v.x;  xq.y -= cq * v.y;  xq.z -= cq * v.z;  xq.w -= cq * v.w;
        xk.x -= ck * v.x;  xk.y -= ck * v.y;  xk.z -= ck * v.z;  xk.w -= ck * v.w;
    }

    // ---- RoPE from SMEM table (conflict-free 128-bit LDS) ----
    const float4 cs = reinterpret_cast<const float4*>(s_cs)[lane];  // (c0,s0,c1,s1)

    float4 oq, ok;
    oq.x = xq.x * cs.x - xq.y * cs.y;
    oq.y = xq.x * cs.y + xq.y * cs.x;
    oq.z = xq.z * cs.z - xq.w * cs.w;
    oq.w = xq.z * cs.w + xq.w * cs.z;
    ok.x = xk.x * cs.x - xk.y * cs.y;
    ok.y = xk.x * cs.y + xk.y * cs.x;
    ok.z = xk.z * cs.z - xk.w * cs.w;
    ok.w = xk.z * cs.w + xk.w * cs.z;

    float4* out4 = reinterpret_cast<float4*>(out);
    __stcs(out4 + off, oq);                              // q half
    __stcs(out4 + (size_t)NVEC * 32 + off, ok);          // k half
}

extern "C" void kernel_launch(void* const* d_in, const int* in_sizes, int n_in,
                              void* d_out, int out_size) {
    const float* q    = (const float*)d_in[0];
    const float* k    = (const float*)d_in[1];
    const float* pos  = (const float*)d_in[2];
    const float* refl = (const float*)d_in[3];
    float* out = (float*)d_out;

    // one warp per (b,s,h): 262144 warps, 8 per block -> 32768 blocks
    hh_rope_kernel<<<NVEC / 8, 256>>>(q, k, pos, refl, out);
}

// round 8
// speedup vs baseline: 1.0940x; 1.0031x over previous
#include <cuda_runtime.h>
#include <cuda_bf16.h>
#include <cstdint>

// FlaxHouseholderRoPE: B=2, S=4096, H=32, D=128, R=2, fp32. SINGLE kernel,
// no SMEM, no barrier, no table.
// Inputs: q (B,S,H,D), k (B,S,H,D), pos (S), reflectors (H,R,D)  [f32]
// Output: concat(q_out, k_out).
//
// One warp per (b,s,h), processing q AND k. Each lane computes its own two
// (cos,sin) pairs inline with Cody-Waite reduction + MUFU sin/cos (~16 instrs,
// err ~1e-6) — scheduled right after the streamed loads so MUFU latency hides
// under LDG latency. Householder: fused 3-value butterfly (dot_q, dot_k, |v|^2)
// per reflection — bit-for-bit the reference recurrence coef = 2*dot/(|v|^2+eps).

#define SS 4096
#define HH 32
#define NVEC (2 * SS * HH)        // 262144 vectors per tensor

__device__ __forceinline__ float dot4(float4 a, float4 b) {
    return a.x * b.x + a.y * b.y + a.z * b.z + a.w * b.w;
}

__global__ __launch_bounds__(256)
void hh_rope_kernel(const float* __restrict__ q,
                    const float* __restrict__ k,
                    const float* __restrict__ pos,
                    const float* __restrict__ refl,
                    float* __restrict__ out) {
    const int tid  = threadIdx.x;
    const int warp = tid >> 5;
    const int lane = tid & 31;
    const int idx  = blockIdx.x * 8 + warp;          // (b*S+s)*H + h
    const int h    = idx & (HH - 1);
    const int s    = (idx >> 5) & (SS - 1);

    // ---- streamed loads FIRST (coalesced LDG.128) ----
    const size_t off = (size_t)idx * 32 + lane;
    float4 xq = __ldcs(reinterpret_cast<const float4*>(q) + off);
    float4 xk = __ldcs(reinterpret_cast<const float4*>(k) + off);

    // ---- inline trig for this lane's two pairs (overlaps LDG latency) ----
    // pair indices: i0 = 2*lane, i1 = 2*lane+1
    // inv_freq(i) = 10000^(-2i/128) = exp2(-(2i/128)*log2(10000))
    const float LOG2_BASE = 13.287712379549449f;
    const float p  = pos[s];
    const float f0 = exp2f(-(float)(4 * lane)     * (1.0f / 128.0f) * LOG2_BASE);
    const float f1 = exp2f(-(float)(4 * lane + 2) * (1.0f / 128.0f) * LOG2_BASE);
    const float a0 = p * f0;                          // == reference's fp32 angle
    const float a1 = p * f1;
    // Cody-Waite: a <= 4096 -> n <= 652; n*6.28125 exact in fp32
    const float INV2PI = 0.15915494309189535f;
    const float C1 = 6.28125f;
    const float C2 = 1.9353071795864769e-3f;          // 2*pi - C1
    const float n0 = rintf(a0 * INV2PI);
    const float n1 = rintf(a1 * INV2PI);
    float r0 = fmaf(-n0, C1, a0);  r0 = fmaf(-n0, C2, r0);
    float r1 = fmaf(-n1, C1, a1);  r1 = fmaf(-n1, C2, r1);
    const float c0 = __cosf(r0), s0 = __sinf(r0);     // MUFU on reduced range
    const float c1 = __cosf(r1), s1 = __sinf(r1);

    // ---- two sequential Householder reflections, fused 3-value butterfly ----
    #pragma unroll
    for (int r = 0; r < 2; ++r) {
        const float4 v = __ldg(reinterpret_cast<const float4*>(refl)
                               + (h * 2 + r) * 32 + lane);   // L1 hit after wave 1
        float dq = dot4(xq, v);
        float dk = dot4(xk, v);
        float sq = dot4(v, v);
        #pragma unroll
        for (int o = 16; o; o >>= 1) {
            dq += __shfl_xor_sync(0xffffffffu, dq, o);
            dk += __shfl_xor_sync(0xffffffffu, dk, o);
            sq += __shfl_xor_sync(0xffffffffu, sq, o);
        }
        const float inv = __frcp_rn(sq + 1e-6f);
        const float cq = 2.0f * dq * inv;
        const float ck = 2.0f * dk * inv;
        xq.x -= cq * v.x;  xq.y -= cq * v.y;  xq.z -= cq * v.z;  xq.w -= cq * v.w;
        xk.x -= ck * v.x;  xk.y -= ck * v.y;  xk.z -= ck * v.z;  xk.w -= ck * v.w;
    }

    // ---- RoPE with in-register cos/sin ----
    float4 oq, ok;
    oq.x = xq.x * c0 - xq.y * s0;
    oq.y = xq.x * s0 + xq.y * c0;
    oq.z = xq.z * c1 - xq.w * s1;
    oq.w = xq.z * s1 + xq.w * c1;
    ok.x = xk.x * c0 - xk.y * s0;
    ok.y = xk.x * s0 + xk.y * c0;
    ok.z = xk.z * c1 - xk.w * s1;
    ok.w = xk.z * s1 + xk.w * c1;

    float4* out4 = reinterpret_cast<float4*>(out);
    __stcs(out4 + off, oq);                              // q half
    __stcs(out4 + (size_t)NVEC * 32 + off, ok);          // k half
}

extern "C" void kernel_launch(void* const* d_in, const int* in_sizes, int n_in,
                              void* d_out, int out_size) {
    const float* q    = (const float*)d_in[0];
    const float* k    = (const float*)d_in[1];
    const float* pos  = (const float*)d_in[2];
    const float* refl = (const float*)d_in[3];
    float* out = (float*)d_out;

    // one warp per (b,s,h): 262144 warps, 8 per block -> 32768 blocks
    hh_rope_kernel<<<NVEC / 8, 256>>>(q, k, pos, refl, out);
}